// round 3
// baseline (speedup 1.0000x reference)
#include <cuda_runtime.h>
#include <math_constants.h>
#include <cstdint>

#define BM   128
#define BN   128
#define BK   16
#define NT   256
#define KDIM 2048
#define NEXP 64
#define NKT  (KDIM / BK)

typedef unsigned long long ull;

__device__ __forceinline__ ull pack2(float lo, float hi) {
    ull r;
    asm("mov.b64 %0, {%1, %2};" : "=l"(r) : "f"(lo), "f"(hi));
    return r;
}
__device__ __forceinline__ void unpack2(ull v, float& lo, float& hi) {
    asm("mov.b64 {%0, %1}, %2;" : "=f"(lo), "=f"(hi) : "l"(v));
}
// Packed dual-FP32 FMA: d = a * b + d  (sm_100+ FFMA2; ptxas never auto-fuses)
__device__ __forceinline__ void ffma2(ull& d, ull a, ull b) {
    asm("fma.rn.f32x2 %0, %1, %2, %0;" : "+l"(d) : "l"(a), "l"(b));
}

__global__ void __launch_bounds__(NT, 2)
routing_kernel(const float* __restrict__ x,
               const float* __restrict__ wg,
               const float* __restrict__ wn,
               const float* __restrict__ noise,
               float* __restrict__ out)
{
    __shared__ __align__(16) float As[2][BK * BM];
    __shared__ __align__(16) float Bs[2][BK * BN];

    const int tid = threadIdx.x;
    const int tx  = tid & 15;   // col-group 0..15  (cols 8*tx .. 8*tx+7)
    const int ty  = tid >> 4;   // row-group 0..15  (rows 8*ty .. 8*ty+7)
    const int m0  = blockIdx.x * BM;

    // ---- zero this block's slice of out (harness poisons d_out) ----
    {
        float4 z = make_float4(0.f, 0.f, 0.f, 0.f);
        float4* ob = reinterpret_cast<float4*>(out + (size_t)m0 * NEXP);
        #pragma unroll
        for (int i = 0; i < (BM * NEXP / 4) / NT; ++i)
            ob[tid + i * NT] = z;
    }

    // ---- global-load index precompute ----
    // A tile: 512 float4 slots; this thread takes slot tid (rows 0..63) and tid+256 (rows 64..127)
    const int rowA = tid >> 2;          // 0..63
    const int kqA  = (tid & 3) * 4;     // 0,4,8,12 : k-offset within chunk
    // B tile: 512 float4 slots; slot tid -> k 0..7, slot tid+256 -> k 8..15
    const int kB   = tid >> 5;          // 0..7
    const int colB = (tid & 31) * 4;    // 0..124

    const float* xA0 = x + (size_t)(m0 + rowA) * KDIM + kqA;
    const float* xA1 = xA0 + (size_t)64 * KDIM;
    // fused B: cols [0,64) from w_gate, [64,128) from w_noise (both row-major [2048,64])
    const float* wB  = (colB < NEXP) ? (wg + colB) : (wn + (colB - NEXP));

    // 32 packed accumulators: acc[mp][c] holds rows (8*ty+2*mp, 8*ty+2*mp+1), col 8*tx+c
    ull acc[4][8];
    #pragma unroll
    for (int i = 0; i < 4; ++i)
        #pragma unroll
        for (int j = 0; j < 8; ++j) acc[i][j] = 0ull;

    float4 ra0, ra1, rb0, rb1;

    // ---- prologue: chunk 0 -> smem buf 0 ----
    ra0 = *reinterpret_cast<const float4*>(xA0);
    ra1 = *reinterpret_cast<const float4*>(xA1);
    rb0 = *reinterpret_cast<const float4*>(wB + (size_t)kB * NEXP);
    rb1 = *reinterpret_cast<const float4*>(wB + (size_t)(kB + 8) * NEXP);
    {
        float* A = As[0];
        float* B = Bs[0];
        A[(kqA + 0) * BM + rowA] = ra0.x;  A[(kqA + 1) * BM + rowA] = ra0.y;
        A[(kqA + 2) * BM + rowA] = ra0.z;  A[(kqA + 3) * BM + rowA] = ra0.w;
        A[(kqA + 0) * BM + rowA + 64] = ra1.x;  A[(kqA + 1) * BM + rowA + 64] = ra1.y;
        A[(kqA + 2) * BM + rowA + 64] = ra1.z;  A[(kqA + 3) * BM + rowA + 64] = ra1.w;
        *reinterpret_cast<float4*>(&B[kB * BN + colB])       = rb0;
        *reinterpret_cast<float4*>(&B[(kB + 8) * BN + colB]) = rb1;
    }
    __syncthreads();

    // ---- K loop: double-buffered, register-staged prefetch, 1 sync/iter ----
    for (int kt = 0; kt < NKT; ++kt) {
        const int  buf  = kt & 1;
        const bool more = (kt + 1 < NKT);
        if (more) {
            const float* xa = xA0 + (size_t)(kt + 1) * BK;
            ra0 = *reinterpret_cast<const float4*>(xa);
            ra1 = *reinterpret_cast<const float4*>(xa + (size_t)64 * KDIM);
            const float* wb = wB + (size_t)(kt + 1) * BK * NEXP;
            rb0 = *reinterpret_cast<const float4*>(wb + (size_t)kB * NEXP);
            rb1 = *reinterpret_cast<const float4*>(wb + (size_t)(kB + 8) * NEXP);
        }

        const float* Ab = As[buf] + ty * 8;
        const float* Bb = Bs[buf] + tx * 8;
        #pragma unroll
        for (int kk = 0; kk < BK; ++kk) {
            ulonglong2 a01 = *reinterpret_cast<const ulonglong2*>(Ab + kk * BM);
            ulonglong2 a23 = *reinterpret_cast<const ulonglong2*>(Ab + kk * BM + 4);
            float4 b0 = *reinterpret_cast<const float4*>(Bb + kk * BN);
            float4 b1 = *reinterpret_cast<const float4*>(Bb + kk * BN + 4);
            ull bb[8];
            bb[0] = pack2(b0.x, b0.x);  bb[1] = pack2(b0.y, b0.y);
            bb[2] = pack2(b0.z, b0.z);  bb[3] = pack2(b0.w, b0.w);
            bb[4] = pack2(b1.x, b1.x);  bb[5] = pack2(b1.y, b1.y);
            bb[6] = pack2(b1.z, b1.z);  bb[7] = pack2(b1.w, b1.w);
            #pragma unroll
            for (int c = 0; c < 8; ++c) {
                ffma2(acc[0][c], a01.x, bb[c]);
                ffma2(acc[1][c], a01.y, bb[c]);
                ffma2(acc[2][c], a23.x, bb[c]);
                ffma2(acc[3][c], a23.y, bb[c]);
            }
        }

        if (more) {
            float* A = As[buf ^ 1];
            float* B = Bs[buf ^ 1];
            A[(kqA + 0) * BM + rowA] = ra0.x;  A[(kqA + 1) * BM + rowA] = ra0.y;
            A[(kqA + 2) * BM + rowA] = ra0.z;  A[(kqA + 3) * BM + rowA] = ra0.w;
            A[(kqA + 0) * BM + rowA + 64] = ra1.x;  A[(kqA + 1) * BM + rowA + 64] = ra1.y;
            A[(kqA + 2) * BM + rowA + 64] = ra1.z;  A[(kqA + 3) * BM + rowA + 64] = ra1.w;
            *reinterpret_cast<float4*>(&B[kB * BN + colB])       = rb0;
            *reinterpret_cast<float4*>(&B[(kB + 8) * BN + colB]) = rb1;
        }
        __syncthreads();
    }

    // ---- epilogue, fully in registers ----
    // Thread owns rows (8*ty + r), cols (8*tx + c). Cols 0..63 = gate logits,
    // cols 64..127 = pre-softplus noise logits. Lane pairing: tx and tx+8 are
    // lane^8 within a half-warp, so shfl_xor(...,8) swaps gate<->noise halves.
    const unsigned FULL = 0xffffffffu;

    #pragma unroll
    for (int r = 0; r < 8; ++r) {
        float v[8];
        #pragma unroll
        for (int c = 0; c < 8; ++c) {
            float lo, hi;
            unpack2(acc[r >> 1][c], lo, hi);
            v[c] = (r & 1) ? hi : lo;
        }
        // softplus(x) + eps  (stable: max(x,0) + log1p(exp(-|x|)))
        float sp[8];
        #pragma unroll
        for (int c = 0; c < 8; ++c) {
            float t = v[c];
            sp[c] = fmaxf(t, 0.f) + log1pf(expf(-fabsf(t))) + 0.01f;
        }

        const int grow = m0 + ty * 8 + r;
        float nn[8] = {0.f, 0.f, 0.f, 0.f, 0.f, 0.f, 0.f, 0.f};
        if (tx < 8) {
            const float4* np =
                reinterpret_cast<const float4*>(noise + (size_t)grow * NEXP + tx * 8);
            float4 n0 = np[0], n1 = np[1];
            nn[0] = n0.x; nn[1] = n0.y; nn[2] = n0.z; nn[3] = n0.w;
            nn[4] = n1.x; nn[5] = n1.y; nn[6] = n1.z; nn[7] = n1.w;
        }

        // local top-2 (ascending index scan + strict '>' => lowest-index tie-break)
        float v1 = -CUDART_INF_F, v2 = -CUDART_INF_F;
        int   i1 = 1 << 20,       i2 = 1 << 20;
        #pragma unroll
        for (int c = 0; c < 8; ++c) {
            float spo = __shfl_xor_sync(FULL, sp[c], 8);   // partner's softplus
            float val = (tx < 8) ? (v[c] + nn[c] * spo) : -CUDART_INF_F;
            int   e   = tx * 8 + c;
            if (val > v1) { v2 = v1; i2 = i1; v1 = val; i1 = e; }
            else if (val > v2) { v2 = val; i2 = e; }
        }

        // butterfly merge across the 8 gate lanes (xor 1,2,4 stays in-group)
        #pragma unroll
        for (int d = 1; d < 8; d <<= 1) {
            float ov1 = __shfl_xor_sync(FULL, v1, d);
            int   oi1 = __shfl_xor_sync(FULL, i1, d);
            float ov2 = __shfl_xor_sync(FULL, v2, d);
            int   oi2 = __shfl_xor_sync(FULL, i2, d);
            bool ofirst = (ov1 > v1) || (ov1 == v1 && oi1 < i1);
            if (ofirst) {
                bool mine2 = (v1 > ov2) || (v1 == ov2 && i1 < oi2);
                v2 = mine2 ? v1 : ov2;
                i2 = mine2 ? i1 : oi2;
                v1 = ov1;  i1 = oi1;
            } else {
                bool osec = (ov1 > v2) || (ov1 == v2 && oi1 < i2);
                if (osec) { v2 = ov1; i2 = oi1; }
            }
        }

        // softmax over [v1, v2] (v1 >= v2) and scatter
        if (tx == 0) {
            float ex = expf(v2 - v1);
            float g1 = 1.f / (1.f + ex);
            out[(size_t)grow * NEXP + i1] = g1;
            out[(size_t)grow * NEXP + i2] = ex * g1;
        }
    }
}

extern "C" void kernel_launch(void* const* d_in, const int* in_sizes, int n_in,
                              void* d_out, int out_size)
{
    (void)in_sizes; (void)n_in; (void)out_size;
    const float* x  = (const float*)d_in[0];
    const float* wg = (const float*)d_in[1];
    const float* wn = (const float*)d_in[2];
    const float* nz = (const float*)d_in[3];
    float* out = (float*)d_out;

    routing_kernel<<<32768 / BM, NT>>>(x, wg, wn, nz, out);
}

// round 6
// speedup vs baseline: 1.0301x; 1.0301x over previous
#include <cuda_runtime.h>
#include <math_constants.h>
#include <cstdint>

#define BM     128
#define NT     256
#define KDIM   2048
#define NEXP   64
#define BK     16
#define NKT    (KDIM / BK)          // 128
#define STAGES 4
#define A_STRIDE 20                  // floats per A row in smem (pad: conflict-free, 16B-aligned)
#define STAGE_A  (BM * A_STRIDE)     // 2560 floats
#define STAGE_B  (BK * 128)          // 2048 floats
#define STAGE_F  (STAGE_A + STAGE_B) // 4608 floats
#define SMEM_BYTES (STAGES * STAGE_F * 4)  // 73728 B

typedef unsigned long long ull;

__device__ __forceinline__ ull pack2(float lo, float hi) {
    ull r;
    asm("mov.b64 %0, {%1, %2};" : "=l"(r) : "f"(lo), "f"(hi));
    return r;
}
__device__ __forceinline__ void unpack2(ull v, float& lo, float& hi) {
    asm("mov.b64 {%0, %1}, %2;" : "=f"(lo), "=f"(hi) : "l"(v));
}
// Packed dual-FP32 FMA (sm_100+): d = a * b + d on two lanes at once.
__device__ __forceinline__ void ffma2(ull& d, ull a, ull b) {
    asm("fma.rn.f32x2 %0, %1, %2, %0;" : "+l"(d) : "l"(a), "l"(b));
}
__device__ __forceinline__ void cp16(float* s, const float* g) {
    unsigned sa = (unsigned)__cvta_generic_to_shared(s);
    asm volatile("cp.async.cg.shared.global [%0], [%1], 16;" :: "r"(sa), "l"(g));
}
__device__ __forceinline__ void cp_commit() {
    asm volatile("cp.async.commit_group;");
}
__device__ __forceinline__ void cp_wait2() {
    asm volatile("cp.async.wait_group 2;");
}

__global__ void __launch_bounds__(NT, 2)
routing_kernel(const float* __restrict__ x,
               const float* __restrict__ wg,
               const float* __restrict__ wn,
               const float* __restrict__ noise,
               float* __restrict__ out)
{
    extern __shared__ __align__(16) float smem[];

    const int tid = threadIdx.x;
    const int tx  = tid & 15;    // col group: gate cols [4tx,4tx+4), noise cols [64+4tx, ...)
    const int ty  = tid >> 4;    // row group: rows [8ty, 8ty+8)
    const int m0  = blockIdx.x * BM;

    // ---- zero this block's out slice (harness poisons d_out) ----
    {
        float4 z = make_float4(0.f, 0.f, 0.f, 0.f);
        float4* ob = reinterpret_cast<float4*>(out + (size_t)m0 * NEXP);
        #pragma unroll
        for (int i = 0; i < (BM * NEXP / 4) / NT; ++i)
            ob[tid + i * NT] = z;
    }

    // ---- staging index precompute ----
    // A: 128 rows x 16 k per stage; thread -> row tid>>1, two 16B chunks at k-offset 8*(tid&1), +4
    const int rowA  = tid >> 1;
    const int koffA = (tid & 1) * 8;
    // B: 16 k-rows x 128 cols; thread -> k-row tid>>4, two 16B chunks at col 8*(tid&15), +4
    const int kB = tid >> 4;
    const int cB = (tid & 15) * 8;   // 0..120, never straddles the 64-col wg/wn boundary

    const float* gA   = x + (size_t)(m0 + rowA) * KDIM + koffA;
    const float* wsrc = (cB < NEXP) ? (wg + cB) : (wn + (cB - NEXP));

    // accumulators: acc[m][cp] packs (col 4tx+2cp, col 4tx+2cp+1) for row 8ty+m
    // cp 0,1 = gate cols; cp 2,3 = noise cols (B cols 64+4tx..)
    ull acc[8][4];
    #pragma unroll
    for (int m = 0; m < 8; ++m)
        #pragma unroll
        for (int c = 0; c < 4; ++c) acc[m][c] = 0ull;

    // ---- prologue: stage chunks 0..2 ----
    #pragma unroll
    for (int s = 0; s < STAGES - 1; ++s) {
        float* st = smem + s * STAGE_F;
        const float* ga = gA + s * BK;
        cp16(st + rowA * A_STRIDE + koffA,     ga);
        cp16(st + rowA * A_STRIDE + koffA + 4, ga + 4);
        const float* gb = wsrc + (size_t)(s * BK + kB) * NEXP;
        float* sb = st + STAGE_A + kB * 128 + cB;
        cp16(sb,     gb);
        cp16(sb + 4, gb + 4);
        cp_commit();
    }

    // ---- main loop: 4-stage cp.async pipeline, 1 sync per chunk ----
    for (int kt = 0; kt < NKT; ++kt) {
        cp_wait2();           // group kt complete (<=2 younger pending)
        __syncthreads();      // all warps done with buf (kt-1)%4 compute & see buf kt%4 data

        const int nx = kt + STAGES - 1;
        if (nx < NKT) {       // overwrite buf (kt+3)%4 == (kt-1)%4 (safe after the sync)
            float* st = smem + (nx & (STAGES - 1)) * STAGE_F;
            const float* ga = gA + nx * BK;
            cp16(st + rowA * A_STRIDE + koffA,     ga);
            cp16(st + rowA * A_STRIDE + koffA + 4, ga + 4);
            const float* gb = wsrc + (size_t)(nx * BK + kB) * NEXP;
            float* sb = st + STAGE_A + kB * 128 + cB;
            cp16(sb,     gb);
            cp16(sb + 4, gb + 4);
        }
        cp_commit();          // always commit (possibly empty) to keep group counting uniform

        const float* st = smem + (kt & (STAGES - 1)) * STAGE_F;
        const float* Ab = st + (ty * 8) * A_STRIDE;            // rows 8ty.., stride 20
        const float* Bb = st + STAGE_A + tx * 4;               // cols 4tx..

        #pragma unroll
        for (int kk = 0; kk < BK; ++kk) {
            // B pairs come packed straight out of smem (conflict-free two-phase LDS.128)
            ulonglong2 b01 = *reinterpret_cast<const ulonglong2*>(Bb + kk * 128);
            ulonglong2 b23 = *reinterpret_cast<const ulonglong2*>(Bb + kk * 128 + 64);
            #pragma unroll
            for (int m = 0; m < 8; ++m) {
                float a = Ab[m * A_STRIDE + kk];               // warp-broadcast scalar LDS
                ull aa = pack2(a, a);
                ffma2(acc[m][0], aa, b01.x);
                ffma2(acc[m][1], aa, b01.y);
                ffma2(acc[m][2], aa, b23.x);
                ffma2(acc[m][3], aa, b23.y);
            }
        }
    }

    // ---- epilogue: gate & matching noise cols live in the SAME thread ----
    const unsigned FULL = 0xffffffffu;

    #pragma unroll
    for (int m = 0; m < 8; ++m) {
        const int grow = m0 + ty * 8 + m;

        float g[4], w[4];
        unpack2(acc[m][0], g[0], g[1]);
        unpack2(acc[m][1], g[2], g[3]);
        unpack2(acc[m][2], w[0], w[1]);
        unpack2(acc[m][3], w[2], w[3]);

        float4 nn = *reinterpret_cast<const float4*>(noise + (size_t)grow * NEXP + tx * 4);
        float nv[4] = {nn.x, nn.y, nn.z, nn.w};

        // local top-2 over 4 experts (ascending index + strict '>' => lowest-index tie-break)
        float v1 = -CUDART_INF_F, v2 = -CUDART_INF_F;
        int   i1 = 1 << 20,       i2 = 1 << 20;
        #pragma unroll
        for (int c = 0; c < 4; ++c) {
            float t  = w[c];
            float sp = fmaxf(t, 0.f) + log1pf(expf(-fabsf(t))) + 0.01f;  // softplus+eps
            float val = g[c] + nv[c] * sp;
            int   e   = tx * 4 + c;
            if (val > v1)      { v2 = v1; i2 = i1; v1 = val; i1 = e; }
            else if (val > v2) { v2 = val; i2 = e; }
        }

        // butterfly merge across 16 tx lanes (xor 1,2,4,8 stays within the half-warp)
        #pragma unroll
        for (int d = 1; d < 16; d <<= 1) {
            float ov1 = __shfl_xor_sync(FULL, v1, d);
            int   oi1 = __shfl_xor_sync(FULL, i1, d);
            float ov2 = __shfl_xor_sync(FULL, v2, d);
            int   oi2 = __shfl_xor_sync(FULL, i2, d);
            bool ofirst = (ov1 > v1) || (ov1 == v1 && oi1 < i1);
            if (ofirst) {
                bool mine2 = (v1 > ov2) || (v1 == ov2 && i1 < oi2);
                v2 = mine2 ? v1 : ov2;
                i2 = mine2 ? i1 : oi2;
                v1 = ov1;  i1 = oi1;
            } else {
                bool osec = (ov1 > v2) || (ov1 == v2 && oi1 < i2);
                if (osec) { v2 = ov1; i2 = oi1; }
            }
        }

        // 2-way softmax (v1 >= v2) and scatter
        if (tx == 0) {
            float ex = expf(v2 - v1);
            float g1 = 1.f / (1.f + ex);
            out[(size_t)grow * NEXP + i1] = g1;
            out[(size_t)grow * NEXP + i2] = ex * g1;
        }
    }
}

extern "C" void kernel_launch(void* const* d_in, const int* in_sizes, int n_in,
                              void* d_out, int out_size)
{
    (void)in_sizes; (void)n_in; (void)out_size;
    const float* x  = (const float*)d_in[0];
    const float* wg = (const float*)d_in[1];
    const float* wn = (const float*)d_in[2];
    const float* nz = (const float*)d_in[3];
    float* out = (float*)d_out;

    cudaFuncSetAttribute(routing_kernel,
                         cudaFuncAttributeMaxDynamicSharedMemorySize, SMEM_BYTES);
    routing_kernel<<<32768 / BM, NT, SMEM_BYTES>>>(x, wg, wn, nz, out);
}